// round 1
// baseline (speedup 1.0000x reference)
#include <cuda_runtime.h>
#include <math.h>

#define S_LEN 60
#define D_IN  256
#define NHEAD 16
#define D_K   8

typedef unsigned long long u64;

// Precomputed effective query weights (Q folded into Wk) and bias term.
__device__ float g_weff[NHEAD * D_IN];
__device__ float g_c[NHEAD];

__device__ __forceinline__ u64 fma2(u64 a, u64 b, u64 c) {
    u64 d;
    asm("fma.rn.f32x2 %0, %1, %2, %3;" : "=l"(d) : "l"(a), "l"(b), "l"(c));
    return d;
}
__device__ __forceinline__ u64 add2(u64 a, u64 b) {
    u64 d;
    asm("add.rn.f32x2 %0, %1, %2;" : "=l"(d) : "l"(a), "l"(b));
    return d;
}
__device__ __forceinline__ float sum2(u64 a) {
    float lo = __uint_as_float((unsigned)(a & 0xffffffffull));
    float hi = __uint_as_float((unsigned)(a >> 32));
    return lo + hi;
}

// ---------------------------------------------------------------------------
// Kernel 1: fold Q into Wk:  w_eff[h][i] = (1/sqrt(dk)) * sum_d Q[h,d]*Wk[h*8+d, i]
//           c[h]            = (1/sqrt(dk)) * sum_d Q[h,d]*bk[h*8+d]
// ---------------------------------------------------------------------------
__global__ void precompute_weff(const float* __restrict__ Q,
                                const float* __restrict__ Wk,
                                const float* __restrict__ bk) {
    const float inv_temp = 0.35355339059327373f;  // 1/sqrt(8)
    int i = threadIdx.x;  // 0..255 column
#pragma unroll
    for (int h = 0; h < NHEAD; ++h) {
        float s = 0.f;
#pragma unroll
        for (int d = 0; d < D_K; ++d)
            s += Q[h * D_K + d] * Wk[(h * D_K + d) * D_IN + i];
        g_weff[h * D_IN + i] = s * inv_temp;
    }
    if (i < NHEAD) {
        float s = 0.f;
#pragma unroll
        for (int d = 0; d < D_K; ++d)
            s += Q[i * D_K + d] * bk[i * D_K + d];
        g_c[i] = s * inv_temp;
    }
}

// ---------------------------------------------------------------------------
// Kernel 2: fused attention. One CTA per batch element.
//   smem: v[60][256] | w_eff[16][256] | scores/attn[16][64]
// ---------------------------------------------------------------------------
__global__ __launch_bounds__(256, 2)
void fused_attn_kernel(const float* __restrict__ v_g,
                       const unsigned char* __restrict__ pad_mask,
                       float* __restrict__ out_g,    // [B, 256]
                       float* __restrict__ attn_g,   // [H, B, S]
                       int B) {
    extern __shared__ float smem[];
    float* v_sm = smem;                       // 15360 floats
    float* w_sm = smem + S_LEN * D_IN;        // 4096 floats
    float* sc_sm = w_sm + NHEAD * D_IN;       // 16*64 floats (scores -> attn)
    __shared__ float c_sm[NHEAD];

    const int t = threadIdx.x;
    const int b = blockIdx.x;

    // ---- Phase A: loads ----
    {
        const float4* vg = (const float4*)(v_g + (size_t)b * S_LEN * D_IN);
        float4* vs = (float4*)v_sm;
#pragma unroll
        for (int i = t; i < S_LEN * D_IN / 4; i += 256) vs[i] = vg[i];

        const float4* wg = (const float4*)g_weff;
        float4* ws = (float4*)w_sm;
#pragma unroll
        for (int i = t; i < NHEAD * D_IN / 4; i += 256) ws[i] = wg[i];

        if (t < NHEAD) c_sm[t] = g_c[t];
    }
    __syncthreads();

    // ---- Phase B: scores[h][s] = w_eff[h] . v[s] + c[h] ----
    // Tile: 15 s-groups(4) x 4 h-groups(4) x 4 k-quarters = 240 work threads.
    {
        const int tt = (t < 240) ? t : 239;       // clamp so warp 7 stays converged
        const int sg = tt >> 4;                   // 0..14
        const int hg = (tt >> 2) & 3;             // 0..3
        const int kq = tt & 3;                    // 0..3
        const int s_base = sg * 4;
        const int h_base = hg * 4;

        const ulonglong2* vb = (const ulonglong2*)v_sm;  // [s][64] of (f32x2,f32x2)
        const ulonglong2* wb = (const ulonglong2*)w_sm;  // [h][64]

        u64 acc[4][4];
#pragma unroll
        for (int i = 0; i < 4; ++i)
#pragma unroll
            for (int j = 0; j < 4; ++j) acc[i][j] = 0ull;

        const int k0 = kq * 16;
#pragma unroll 4
        for (int kk = k0; kk < k0 + 16; ++kk) {
            ulonglong2 vv[4], ww[4];
#pragma unroll
            for (int i = 0; i < 4; ++i) vv[i] = vb[(s_base + i) * 64 + kk];
#pragma unroll
            for (int j = 0; j < 4; ++j) ww[j] = wb[(h_base + j) * 64 + kk];
#pragma unroll
            for (int i = 0; i < 4; ++i)
#pragma unroll
                for (int j = 0; j < 4; ++j) {
                    acc[i][j] = fma2(vv[i].x, ww[j].x, acc[i][j]);
                    acc[i][j] = fma2(vv[i].y, ww[j].y, acc[i][j]);
                }
        }

        // reduce across the 4 k-quarter lanes (xor 1, xor 2 within lane group)
#pragma unroll
        for (int i = 0; i < 4; ++i)
#pragma unroll
            for (int j = 0; j < 4; ++j) {
                u64 a = acc[i][j];
                a = add2(a, __shfl_xor_sync(0xffffffffu, a, 1));
                a = add2(a, __shfl_xor_sync(0xffffffffu, a, 2));
                acc[i][j] = a;
            }

        if (t < 240 && kq == 0) {
#pragma unroll
            for (int i = 0; i < 4; ++i)
#pragma unroll
                for (int j = 0; j < 4; ++j)
                    sc_sm[(h_base + j) * 64 + (s_base + i)] =
                        sum2(acc[i][j]) + c_sm[h_base + j];
        }
    }
    __syncthreads();

    // ---- Phase C: masked softmax over s, write attn (smem + global) ----
    {
        const int wid = t >> 5;
        const int lane = t & 31;
        const unsigned char* pm = pad_mask + (size_t)b * S_LEN;

        for (int h = wid; h < NHEAD; h += 8) {
            float x0 = sc_sm[h * 64 + lane];                      // s = lane (<60 always)
            const bool has1 = (lane + 32) < S_LEN;                // s = lane+32
            float x1 = has1 ? sc_sm[h * 64 + lane + 32] : -1e30f;
            if (pm[lane]) x0 = -1e6f;
            if (has1 && pm[lane + 32]) x1 = -1e6f;

            float m = fmaxf(x0, x1);
#pragma unroll
            for (int o = 16; o > 0; o >>= 1)
                m = fmaxf(m, __shfl_xor_sync(0xffffffffu, m, o));

            float e0 = __expf(x0 - m);
            float e1 = has1 ? __expf(x1 - m) : 0.f;
            float ss = e0 + e1;
#pragma unroll
            for (int o = 16; o > 0; o >>= 1)
                ss += __shfl_xor_sync(0xffffffffu, ss, o);
            float inv = 1.0f / ss;

            float a0 = e0 * inv;
            float a1 = e1 * inv;
            sc_sm[h * 64 + lane] = a0;
            if (has1) sc_sm[h * 64 + lane + 32] = a1;

            float* ag = attn_g + ((size_t)h * B + b) * S_LEN;
            ag[lane] = a0;
            if (has1) ag[lane + 32] = a1;
        }
    }
    __syncthreads();

    // ---- Phase D: out[b, h*16+d] = sum_s attn[h][s] * v[s][h*16+d] ----
    {
        const int h = t >> 4;  // t == h*16 + d
        const float* ar = sc_sm + h * 64;
        float a0 = 0.f, a1 = 0.f, a2 = 0.f, a3 = 0.f;
#pragma unroll
        for (int s = 0; s < S_LEN; s += 4) {
            a0 += ar[s + 0] * v_sm[(s + 0) * D_IN + t];
            a1 += ar[s + 1] * v_sm[(s + 1) * D_IN + t];
            a2 += ar[s + 2] * v_sm[(s + 2) * D_IN + t];
            a3 += ar[s + 3] * v_sm[(s + 3) * D_IN + t];
        }
        out_g[(size_t)b * D_IN + t] = (a0 + a1) + (a2 + a3);
    }
}

// ---------------------------------------------------------------------------
extern "C" void kernel_launch(void* const* d_in, const int* in_sizes, int n_in,
                              void* d_out, int out_size) {
    const float* v = (const float*)d_in[0];
    const float* Q = (const float*)d_in[1];
    const float* Wk = (const float*)d_in[2];
    const float* bk = (const float*)d_in[3];
    const unsigned char* pm = (const unsigned char*)d_in[4];

    const int B = in_sizes[0] / (S_LEN * D_IN);

    float* out = (float*)d_out;                      // [B, 256] first
    float* attn = out + (size_t)B * D_IN;            // then [H, B, S]

    precompute_weff<<<1, 256>>>(Q, Wk, bk);

    const size_t smem_bytes =
        (size_t)(S_LEN * D_IN + NHEAD * D_IN + NHEAD * 64) * sizeof(float);
    static bool attr_set = false;
    (void)attr_set;
    cudaFuncSetAttribute(fused_attn_kernel,
                         cudaFuncAttributeMaxDynamicSharedMemorySize,
                         (int)smem_bytes);

    fused_attn_kernel<<<B, 256, smem_bytes>>>(v, pm, out, attn, B);
}

// round 3
// speedup vs baseline: 3.0612x; 3.0612x over previous
#include <cuda_runtime.h>
#include <math.h>

#define S_LEN 60
#define D_IN  256
#define NHEAD 16
#define D_K   8

typedef unsigned long long u64;

// smem layout (in u64 / f32x2 units):
//   v:  60 rows x stride 130 (128 data + 2 pad)
//   w:  16 rows x stride 129 (128 data + 1 pad)
//   sc: 16 x 64 floats (scores -> attn)
#define V_STRIDE 130
#define W_STRIDE 129
#define V_U64    (S_LEN * V_STRIDE)      // 7800
#define W_U64    (NHEAD * W_STRIDE)      // 2064

__device__ float g_weff[NHEAD * D_IN];
__device__ float g_c[NHEAD];

__device__ __forceinline__ u64 fma2(u64 a, u64 b, u64 c) {
    u64 d;
    asm("fma.rn.f32x2 %0, %1, %2, %3;" : "=l"(d) : "l"(a), "l"(b), "l"(c));
    return d;
}
__device__ __forceinline__ float sum2(u64 a) {
    float lo = __uint_as_float((unsigned)(a & 0xffffffffull));
    float hi = __uint_as_float((unsigned)(a >> 32));
    return lo + hi;
}

// ---------------------------------------------------------------------------
// Fold Q into Wk:  w_eff[h][i] = (1/sqrt(dk)) * sum_d Q[h,d]*Wk[h*8+d, i]
// ---------------------------------------------------------------------------
__global__ void precompute_weff(const float* __restrict__ Q,
                                const float* __restrict__ Wk,
                                const float* __restrict__ bk) {
    const float inv_temp = 0.35355339059327373f;  // 1/sqrt(8)
    int i = threadIdx.x;  // 0..255
#pragma unroll
    for (int h = 0; h < NHEAD; ++h) {
        float s = 0.f;
#pragma unroll
        for (int d = 0; d < D_K; ++d)
            s += Q[h * D_K + d] * Wk[(h * D_K + d) * D_IN + i];
        g_weff[h * D_IN + i] = s * inv_temp;
    }
    if (i < NHEAD) {
        float s = 0.f;
#pragma unroll
        for (int d = 0; d < D_K; ++d)
            s += Q[i * D_K + d] * bk[i * D_K + d];
        g_c[i] = s * inv_temp;
    }
}

// ---------------------------------------------------------------------------
// Fused attention: one CTA per batch element.
// ---------------------------------------------------------------------------
__global__ __launch_bounds__(256, 2)
void fused_attn_kernel(const float* __restrict__ v_g,
                       const unsigned char* __restrict__ pad_mask,
                       float* __restrict__ out_g,    // [B, 256]
                       float* __restrict__ attn_g,   // [H, B, S]
                       int B) {
    extern __shared__ u64 smem_u64[];
    u64* v_sm = smem_u64;                               // V_U64
    u64* w_sm = smem_u64 + V_U64;                       // W_U64
    float* sc_sm = (float*)(smem_u64 + V_U64 + W_U64);  // 16*64 floats
    __shared__ float c_sm[NHEAD];

    const int t = threadIdx.x;
    const int b = blockIdx.x;

    // ---- Phase A: stage v and w into padded smem ----
    {
        const float4* vg = (const float4*)(v_g + (size_t)b * (S_LEN * D_IN));
        float2* vd = (float2*)v_sm;
#pragma unroll
        for (int i = t; i < S_LEN * D_IN / 4; i += 256) {   // 3840 float4, 64/row
            float4 x = vg[i];
            int row = i >> 6;
            int c4 = i & 63;
            float2* d = vd + row * V_STRIDE + c4 * 2;
            d[0] = make_float2(x.x, x.y);
            d[1] = make_float2(x.z, x.w);
        }
        const float4* wg = (const float4*)g_weff;
        float2* wd = (float2*)w_sm;
#pragma unroll
        for (int i = t; i < NHEAD * D_IN / 4; i += 256) {   // 1024 float4, 64/row
            float4 x = wg[i];
            int row = i >> 6;
            int c4 = i & 63;
            float2* d = wd + row * W_STRIDE + c4 * 2;
            d[0] = make_float2(x.x, x.y);
            d[1] = make_float2(x.z, x.w);
        }
        if (t < NHEAD) c_sm[t] = g_c[t];
    }
    __syncthreads();

    // ---- Phase B: scores[h][s] = w_eff[h] . v[s] + c[h] ----
    // kq = t&7 (k eighth), hg = (t>>3)&1 (8 heads), sg = t>>4 (4 s rows).
    // u64 k-index kk = kq + 8*it, it = 0..15 -> covers 0..127.
    {
        const int tt = (t < 240) ? t : 239;   // warp 7 upper half: converged dups
        const int kq = tt & 7;
        const int hg = (tt >> 3) & 1;
        const int sg = tt >> 4;               // 0..14

        const u64* vb = v_sm + sg * 4 * V_STRIDE + kq;
        const u64* wb = w_sm + hg * 8 * W_STRIDE + kq;

        u64 acc[4][8];
#pragma unroll
        for (int i = 0; i < 4; ++i)
#pragma unroll
            for (int j = 0; j < 8; ++j) acc[i][j] = 0ull;

#pragma unroll 2
        for (int it = 0; it < 16; ++it) {
            u64 vv[4], ww[8];
#pragma unroll
            for (int i = 0; i < 4; ++i) vv[i] = vb[i * V_STRIDE + it * 8];
#pragma unroll
            for (int j = 0; j < 8; ++j) ww[j] = wb[j * W_STRIDE + it * 8];
#pragma unroll
            for (int i = 0; i < 4; ++i)
#pragma unroll
                for (int j = 0; j < 8; ++j)
                    acc[i][j] = fma2(vv[i], ww[j], acc[i][j]);
        }

        // reduce across the 8 kq lanes (xor 1,2,4) in f32
#pragma unroll
        for (int i = 0; i < 4; ++i)
#pragma unroll
            for (int j = 0; j < 8; ++j) {
                float r = sum2(acc[i][j]);
                r += __shfl_xor_sync(0xffffffffu, r, 1);
                r += __shfl_xor_sync(0xffffffffu, r, 2);
                r += __shfl_xor_sync(0xffffffffu, r, 4);
                if (t < 240 && kq == 0) {
                    int h = hg * 8 + j;
                    sc_sm[h * 64 + sg * 4 + i] = r + c_sm[h];
                }
            }
    }
    __syncthreads();

    // ---- Phase C: masked softmax over s, write attn (smem + global) ----
    {
        const int wid = t >> 5;
        const int lane = t & 31;
        const unsigned char* pm = pad_mask + (size_t)b * S_LEN;

        for (int h = wid; h < NHEAD; h += 8) {
            float x0 = sc_sm[h * 64 + lane];
            const bool has1 = (lane + 32) < S_LEN;
            float x1 = has1 ? sc_sm[h * 64 + lane + 32] : -1e30f;
            if (pm[lane]) x0 = -1e6f;
            if (has1 && pm[lane + 32]) x1 = -1e6f;

            float m = fmaxf(x0, x1);
#pragma unroll
            for (int o = 16; o > 0; o >>= 1)
                m = fmaxf(m, __shfl_xor_sync(0xffffffffu, m, o));

            float e0 = __expf(x0 - m);
            float e1 = has1 ? __expf(x1 - m) : 0.f;
            float ss = e0 + e1;
#pragma unroll
            for (int o = 16; o > 0; o >>= 1)
                ss += __shfl_xor_sync(0xffffffffu, ss, o);
            float inv = 1.0f / ss;

            float a0 = e0 * inv;
            float a1 = e1 * inv;
            sc_sm[h * 64 + lane] = a0;
            if (has1) sc_sm[h * 64 + lane + 32] = a1;

            float* ag = attn_g + ((size_t)h * B + b) * S_LEN;
            ag[lane] = a0;
            if (has1) ag[lane + 32] = a1;
        }
    }
    __syncthreads();

    // ---- Phase D: out[b, h*16+d] = sum_s attn[h][s] * v[s][h*16+d] ----
    {
        const int h = t >> 4;
        const float* vf = (const float*)v_sm;           // row stride 260 floats
        const float4* a4 = (const float4*)(sc_sm + h * 64);
        float acc0 = 0.f, acc1 = 0.f;
#pragma unroll
        for (int q = 0; q < 15; ++q) {
            float4 a = a4[q];
            const float* vr = vf + (q * 4) * (2 * V_STRIDE) + t;
            acc0 += a.x * vr[0];
            acc1 += a.y * vr[2 * V_STRIDE];
            acc0 += a.z * vr[4 * V_STRIDE];
            acc1 += a.w * vr[6 * V_STRIDE];
        }
        out_g[(size_t)b * D_IN + t] = acc0 + acc1;
    }
}

// ---------------------------------------------------------------------------
extern "C" void kernel_launch(void* const* d_in, const int* in_sizes, int n_in,
                              void* d_out, int out_size) {
    const float* v = (const float*)d_in[0];
    const float* Q = (const float*)d_in[1];
    const float* Wk = (const float*)d_in[2];
    const float* bk = (const float*)d_in[3];
    const unsigned char* pm = (const unsigned char*)d_in[4];

    const int B = in_sizes[0] / (S_LEN * D_IN);

    float* out = (float*)d_out;                  // [B, 256]
    float* attn = out + (size_t)B * D_IN;        // [H, B, S]

    precompute_weff<<<1, 256>>>(Q, Wk, bk);

    const size_t smem_bytes = (size_t)(V_U64 + W_U64) * 8 + NHEAD * 64 * 4;
    cudaFuncSetAttribute(fused_attn_kernel,
                         cudaFuncAttributeMaxDynamicSharedMemorySize,
                         (int)smem_bytes);

    fused_attn_kernel<<<B, 256, smem_bytes>>>(v, pm, out, attn, B);
}

// round 5
// speedup vs baseline: 3.5074x; 1.1457x over previous
#include <cuda_runtime.h>
#include <math.h>

#define S_LEN 60
#define D_IN  256
#define NHEAD 16
#define SC_STRIDE 68   // padded score row stride (floats)

typedef unsigned long long u64;

__device__ __align__(16) float g_weff[NHEAD * D_IN];
__device__ float g_c[NHEAD];

__device__ __forceinline__ u64 fma2(u64 a, u64 b, u64 c) {
    u64 d;
    asm("fma.rn.f32x2 %0, %1, %2, %3;" : "=l"(d) : "l"(a), "l"(b), "l"(c));
    return d;
}
__device__ __forceinline__ u64 mul2(u64 a, u64 b) {
    u64 d;
    asm("mul.rn.f32x2 %0, %1, %2;" : "=l"(d) : "l"(a), "l"(b));
    return d;
}
__device__ __forceinline__ float sum2(u64 a) {
    float lo = __uint_as_float((unsigned)(a & 0xffffffffull));
    float hi = __uint_as_float((unsigned)(a >> 32));
    return lo + hi;
}
__device__ __forceinline__ u64 pack2(float lo, float hi) {
    u64 d;
    asm("mov.b64 %0, {%1, %2};" : "=l"(d) : "f"(lo), "f"(hi));
    return d;
}

// ---------------------------------------------------------------------------
// Fold Q into Wk:  w_eff[h][i] = (1/sqrt(dk)) * sum_d Q[h,d]*Wk[h*8+d, i]
// ---------------------------------------------------------------------------
__global__ void precompute_weff(const float* __restrict__ Q,
                                const float* __restrict__ Wk,
                                const float* __restrict__ bk) {
    const float inv_temp = 0.35355339059327373f;  // 1/sqrt(8)
    int i = threadIdx.x;  // 0..255
#pragma unroll
    for (int h = 0; h < NHEAD; ++h) {
        float s = 0.f;
#pragma unroll
        for (int d = 0; d < 8; ++d)
            s += Q[h * 8 + d] * Wk[(h * 8 + d) * D_IN + i];
        g_weff[h * D_IN + i] = s * inv_temp;
    }
    if (i < NHEAD) {
        float s = 0.f;
#pragma unroll
        for (int d = 0; d < 8; ++d)
            s += Q[i * 8 + d] * bk[i * 8 + d];
        g_c[i] = s * inv_temp;
    }
}

// ---------------------------------------------------------------------------
// Fused attention: one CTA per batch element.
// smem: v[60][256] floats (linear) | sc[16][SC_STRIDE]
// ---------------------------------------------------------------------------
__global__ __launch_bounds__(256, 2)
void fused_attn_kernel(const float* __restrict__ v_g,
                       const unsigned char* __restrict__ pad_mask,
                       float* __restrict__ out_g,    // [B, 256]
                       float* __restrict__ attn_g,   // [H, B, S]
                       int B) {
    extern __shared__ float smem_f[];
    float* v_sm = smem_f;                             // 15360 floats
    float* sc_sm = smem_f + S_LEN * D_IN;             // 16*SC_STRIDE floats
    __shared__ float c_sm[NHEAD];

    const int t = threadIdx.x;
    const int b = blockIdx.x;
    const int wid = t >> 5;
    const int lane = t & 31;

    // ---- w preload into registers (8 heads x 4 u64 per lane) ----
    const int hh = wid & 1;       // head half: h in [8*hh, 8*hh+8)
    const int sq = wid >> 1;      // s quarter: rows [15*sq, 15*sq+15)
    u64 w0x[8], w0y[8], w1x[8], w1y[8];
    {
        const float4* wg4 = (const float4*)g_weff;   // 64 float4 per head row
#pragma unroll
        for (int j = 0; j < 8; ++j) {
            int h = hh * 8 + j;
            float4 a = __ldg(wg4 + h * 64 + lane);        // floats 4l..4l+3
            float4 c = __ldg(wg4 + h * 64 + 32 + lane);   // floats 128+4l..
            w0x[j] = pack2(a.x, a.y);
            w0y[j] = pack2(a.z, a.w);
            w1x[j] = pack2(c.x, c.y);
            w1y[j] = pack2(c.z, c.w);
        }
    }

    // ---- Phase A: stage v (linear, 128-bit copies) ----
    {
        const float4* vg = (const float4*)(v_g + (size_t)b * (S_LEN * D_IN));
        float4* vs = (float4*)v_sm;
#pragma unroll
        for (int i = t; i < S_LEN * D_IN / 4; i += 256) vs[i] = vg[i];
        if (t < NHEAD) c_sm[t] = g_c[t];
    }
    __syncthreads();

    // ---- Phase B: scores. Lane owns floats {4l..4l+3, 128+4l..128+4l+3} ----
    {
        const bool hi4 = (lane & 16) != 0;
        const bool hi3 = (lane & 8) != 0;
        const bool hi2 = (lane & 4) != 0;
        const int my_h = hh * 8 + (lane >> 2);
        const float c_h = c_sm[my_h];
        const bool store_lane = (lane & 3) == 0;
        float* sc_dst = sc_sm + my_h * SC_STRIDE + sq * 15;

        const ulonglong2* vb =
            (const ulonglong2*)v_sm + (size_t)(sq * 15) * 16 + (lane >> 1);
        // NOTE: row = 256 floats = 16 ulonglong2? No: 256 floats = 128 u64 = 64 u2.
        const ulonglong2* vrow =
            (const ulonglong2*)v_sm + (size_t)(sq * 15) * 64 + lane;
        (void)vb;

#pragma unroll 3
        for (int r = 0; r < 15; ++r) {
            ulonglong2 v0 = vrow[0];     // u64 idx 2l, 2l+1  (floats 4l..4l+3)
            ulonglong2 v1 = vrow[32];    // u64 idx 64+2l, 64+2l+1
            float p[8];
#pragma unroll
            for (int j = 0; j < 8; ++j) {
                u64 a = mul2(v0.x, w0x[j]);
                a = fma2(v0.y, w0y[j], a);
                a = fma2(v1.x, w1x[j], a);
                a = fma2(v1.y, w1y[j], a);
                p[j] = sum2(a);
            }
            // value-halving reduction tree: xor16 (4 shfl), xor8 (2), xor4 (1)
            float q[4];
#pragma unroll
            for (int j = 0; j < 4; ++j) {
                float mine = hi4 ? p[j + 4] : p[j];
                float send = hi4 ? p[j] : p[j + 4];
                q[j] = mine + __shfl_xor_sync(0xffffffffu, send, 16);
            }
            float r2[2];
#pragma unroll
            for (int j = 0; j < 2; ++j) {
                float mine = hi3 ? q[j + 2] : q[j];
                float send = hi3 ? q[j] : q[j + 2];
                r2[j] = mine + __shfl_xor_sync(0xffffffffu, send, 8);
            }
            {
                float mine = hi2 ? r2[1] : r2[0];
                float send = hi2 ? r2[0] : r2[1];
                float s = mine + __shfl_xor_sync(0xffffffffu, send, 4);
                s += __shfl_xor_sync(0xffffffffu, s, 1);
                s += __shfl_xor_sync(0xffffffffu, s, 2);
                if (store_lane) sc_dst[r] = s + c_h;
            }
            vrow += 64;
        }
    }
    __syncthreads();

    // ---- Phase C: masked softmax over s, write attn (smem + global) ----
    {
        const unsigned char* pm = pad_mask + (size_t)b * S_LEN;
        for (int h = wid; h < NHEAD; h += 8) {
            float x0 = sc_sm[h * SC_STRIDE + lane];
            const bool has1 = (lane + 32) < S_LEN;
            float x1 = has1 ? sc_sm[h * SC_STRIDE + lane + 32] : -1e30f;
            if (pm[lane]) x0 = -1e6f;
            if (has1 && pm[lane + 32]) x1 = -1e6f;

            float m = fmaxf(x0, x1);
#pragma unroll
            for (int o = 16; o > 0; o >>= 1)
                m = fmaxf(m, __shfl_xor_sync(0xffffffffu, m, o));

            float e0 = __expf(x0 - m);
            float e1 = has1 ? __expf(x1 - m) : 0.f;
            float ss = e0 + e1;
#pragma unroll
            for (int o = 16; o > 0; o >>= 1)
                ss += __shfl_xor_sync(0xffffffffu, ss, o);
            float inv = 1.0f / ss;

            float a0 = e0 * inv;
            float a1 = e1 * inv;
            sc_sm[h * SC_STRIDE + lane] = a0;
            if (has1) sc_sm[h * SC_STRIDE + lane + 32] = a1;

            float* ag = attn_g + ((size_t)h * B + b) * S_LEN;
            ag[lane] = a0;
            if (has1) ag[lane + 32] = a1;
        }
    }
    __syncthreads();

    // ---- Phase D: out[b, h*16+d] = sum_s attn[h][s] * v[s][h*16+d] ----
    {
        const int h = t >> 4;   // t == h*16 + d
        const float4* a4 = (const float4*)(sc_sm + h * SC_STRIDE);  // 68%4==0
        float acc0 = 0.f, acc1 = 0.f;
#pragma unroll
        for (int q = 0; q < 15; ++q) {
            float4 a = a4[q];
            const float* vr = v_sm + (q * 4) * D_IN + t;
            acc0 += a.x * vr[0];
            acc1 += a.y * vr[D_IN];
            acc0 += a.z * vr[2 * D_IN];
            acc1 += a.w * vr[3 * D_IN];
        }
        out_g[(size_t)b * D_IN + t] = acc0 + acc1;
    }
}

// ---------------------------------------------------------------------------
extern "C" void kernel_launch(void* const* d_in, const int* in_sizes, int n_in,
                              void* d_out, int out_size) {
    const float* v = (const float*)d_in[0];
    const float* Q = (const float*)d_in[1];
    const float* Wk = (const float*)d_in[2];
    const float* bk = (const float*)d_in[3];
    const unsigned char* pm = (const unsigned char*)d_in[4];

    const int B = in_sizes[0] / (S_LEN * D_IN);

    float* out = (float*)d_out;                  // [B, 256]
    float* attn = out + (size_t)B * D_IN;        // [H, B, S]

    precompute_weff<<<1, 256>>>(Q, Wk, bk);

    const size_t smem_bytes =
        (size_t)(S_LEN * D_IN + NHEAD * SC_STRIDE) * sizeof(float);
    cudaFuncSetAttribute(fused_attn_kernel,
                         cudaFuncAttributeMaxDynamicSharedMemorySize,
                         (int)smem_bytes);

    fused_attn_kernel<<<B, 256, smem_bytes>>>(v, pm, out, attn, B);
}